// round 10
// baseline (speedup 1.0000x reference)
#include <cuda_runtime.h>
#include <math.h>

#define B_NO   8
#define T_LEN  10000
#define E_NUM  1000
#define I_NUM  250
#define SUB_NO 8
#define HID_NO 16
#define CBAS   30
#define T_NO   200

// output layout: final | sub_out | C_syn_e | C_syn_i
#define FINAL_OFF  0
#define SUBOUT_OFF (B_NO * T_LEN)                       // 80000
#define CE_OFF     (SUBOUT_OFF + B_NO * T_LEN * SUB_NO) // 720000
#define CI_OFF     (CE_OFF + SUB_NO * E_NUM)            // 728000

// ---------------- device scratch ----------------
__device__ __align__(16) float g_kern_e[SUB_NO * T_NO * HID_NO];  // [s][tau][h]
__device__ __align__(16) float g_kern_i[SUB_NO * T_NO * HID_NO];
__device__ float g_syn_e[B_NO * SUB_NO * T_LEN];                  // [b][s][t]
__device__ float g_syn_i[B_NO * SUB_NO * T_LEN];
// scaled transposed C: [e][8] floats, e-padded with zeros
__device__ __align__(16) float g_CTe[1024 * 8];
__device__ __align__(16) float g_CTi[256 * 8];

// ---------------- helpers ----------------
__device__ __forceinline__ float2 ffma2(float2 a, float2 b, float2 c) {
    union U { float2 f; unsigned long long u; };
    U A, B, C, D;
    A.f = a; B.f = b; C.f = c;
    asm("fma.rn.f32x2 %0, %1, %2, %3;" : "=l"(D.u) : "l"(A.u), "l"(B.u), "l"(C.u));
    return D.f;
}

__device__ __forceinline__ float tanh_fast(float x) {
    float e = __expf(2.0f * x);
    return 1.0f - __fdividef(2.0f, e + 1.0f);
}

// ---------------- K0: softmax + scaled transposed copies (+padding zero) ---------
__global__ void softmax_kernel(const float* __restrict__ Cer,
                               const float* __restrict__ Cir,
                               const float* __restrict__ Es,
                               const float* __restrict__ Is,
                               float* __restrict__ out) {
    int idx = blockIdx.x * blockDim.x + threadIdx.x;
    if (idx < E_NUM) {
        float u[SUB_NO], p[SUB_NO];
        float m = -1e30f;
#pragma unroll
        for (int s = 0; s < SUB_NO; ++s) { u[s] = Cer[s * E_NUM + idx] * 10000.0f; m = fmaxf(m, u[s]); }
        float sum = 0.0f;
#pragma unroll
        for (int s = 0; s < SUB_NO; ++s) { p[s] = expf(u[s] - m); sum += p[s]; }
        float inv = 1.0f / sum;
        float sc  = expf(Es[idx]);
#pragma unroll
        for (int s = 0; s < SUB_NO; ++s) {
            float v = p[s] * inv;
            out[CE_OFF + s * E_NUM + idx] = v;
            g_CTe[idx * 8 + s] = v * sc;
        }
    } else if (idx < E_NUM + I_NUM) {
        int j = idx - E_NUM;
        float u[SUB_NO], p[SUB_NO];
        float m = -1e30f;
#pragma unroll
        for (int s = 0; s < SUB_NO; ++s) { u[s] = Cir[s * I_NUM + j] * 10000.0f; m = fmaxf(m, u[s]); }
        float sum = 0.0f;
#pragma unroll
        for (int s = 0; s < SUB_NO; ++s) { p[s] = expf(u[s] - m); sum += p[s]; }
        float inv = 1.0f / sum;
        float sc  = expf(Is[j]);
#pragma unroll
        for (int s = 0; s < SUB_NO; ++s) {
            float v = p[s] * inv;
            out[CI_OFF + s * I_NUM + j] = v;
            g_CTi[j * 8 + s] = v * sc;
        }
    } else if (idx < E_NUM + I_NUM + 24) {       // zero-pad C_e rows [1000,1024)
        int row = E_NUM + (idx - (E_NUM + I_NUM));
#pragma unroll
        for (int s = 0; s < SUB_NO; ++s) g_CTe[row * 8 + s] = 0.0f;
    } else if (idx < E_NUM + I_NUM + 24 + 6) {   // zero-pad C_i rows [250,256)
        int row = I_NUM + (idx - (E_NUM + I_NUM + 24));
#pragma unroll
        for (int s = 0; s < SUB_NO; ++s) g_CTi[row * 8 + s] = 0.0f;
    }
}

// ---------------- K1: temporal kernels from cosine basis ----------------
__global__ void kern_kernel(const float* __restrict__ W_e,
                            const float* __restrict__ W_i) {
    __shared__ float bas[CBAS];
    int tau = blockIdx.x;
    if (threadIdx.x < CBAS) {
        double phi = 0.5 * M_PI * (double)threadIdx.x;
        double raw = 7.5 * log((double)tau + 1.0 + 1e-7);
        double v = 0.0;
        if (raw >= phi - M_PI && raw <= phi + M_PI)
            v = 0.5 * cos(raw - phi) + 0.5;
        bas[threadIdx.x] = (float)v;
    }
    __syncthreads();
    int r = threadIdx.x;             // 0..127
    float ae = 0.0f, ai = 0.0f;
#pragma unroll
    for (int c = 0; c < CBAS; ++c) {
        ae = fmaf(W_e[r * CBAS + c], bas[c], ae);
        ai = fmaf(W_i[r * CBAS + c], bas[c], ai);
    }
    int s = r >> 4, h = r & 15;
    g_kern_e[(s * T_NO + tau) * HID_NO + h] = ae;
    g_kern_i[(s * T_NO + tau) * HID_NO + h] = ai;
}

// ---------------- K2: synapse pooling (double-buffered transpose staging) -------
#define PXSTRIDE 257
#define PBUF (32 * PXSTRIDE)        // 8224 floats per buffer
#define PSME_BYTES (2 * PBUF * 4)   // 65792 B

__device__ __forceinline__ void pool_compute_chunk(const float* __restrict__ buf,
                                                   const float* __restrict__ Cg,
                                                   int tid, float2 (&acc)[4]) {
    const float4* Crow = (const float4*)Cg;
#pragma unroll
    for (int el = 0; el < 32; ++el) {
        float x = buf[el * PXSTRIDE + tid];
        float4 cA = __ldg(Crow + el * 2);
        float4 cB = __ldg(Crow + el * 2 + 1);
        float2 vv = make_float2(x, x);
        acc[0] = ffma2(make_float2(cA.x, cA.y), vv, acc[0]);
        acc[1] = ffma2(make_float2(cA.z, cA.w), vv, acc[1]);
        acc[2] = ffma2(make_float2(cB.x, cB.y), vv, acc[2]);
        acc[3] = ffma2(make_float2(cB.z, cB.w), vv, acc[3]);
    }
}

__device__ __forceinline__ void pool_sts(float* __restrict__ buf, int g4, int tr,
                                         const float4 (&v)[8]) {
#pragma unroll
    for (int k = 0; k < 8; ++k) {
        int tcol = tr + 32 * k;
        buf[(g4 + 0) * PXSTRIDE + tcol] = v[k].x;
        buf[(g4 + 1) * PXSTRIDE + tcol] = v[k].y;
        buf[(g4 + 2) * PXSTRIDE + tcol] = v[k].z;
        buf[(g4 + 3) * PXSTRIDE + tcol] = v[k].w;
    }
}

__global__ void __launch_bounds__(256, 3)
pool_kernel(const float* __restrict__ S_e, const float* __restrict__ S_i) {
    extern __shared__ float sX[];    // 2 buffers of PBUF floats

    int tid = threadIdx.x;
    int b = blockIdx.y;
    int t0 = blockIdx.x * 256;
    int t = t0 + tid;
    bool tvalid = (t < T_LEN);

    int g  = tid & 7;                // float4 slot within 32-e chunk
    int tr = tid >> 3;               // base t-row for loads (0..31)
    int g4 = g * 4;

    float2 acc[4];
    float4 v[8];

    // ================= E: 32 chunks of 32 e =================
    {
#pragma unroll
        for (int sp = 0; sp < 4; ++sp) acc[sp] = make_float2(0.f, 0.f);

        // chunk 0 (S_e rows are 4000B -> float4 aligned)
#pragma unroll
        for (int k = 0; k < 8; ++k) {
            int trow = t0 + tr + 32 * k;
            v[k] = (trow < T_LEN)
                   ? *(const float4*)(S_e + (size_t)(b * T_LEN + trow) * E_NUM + g4)
                   : make_float4(0.f, 0.f, 0.f, 0.f);
        }
        pool_sts(sX, g4, tr, v);
        // chunk 1
#pragma unroll
        for (int k = 0; k < 8; ++k) {
            int trow = t0 + tr + 32 * k;
            v[k] = (trow < T_LEN)
                   ? *(const float4*)(S_e + (size_t)(b * T_LEN + trow) * E_NUM + 32 + g4)
                   : make_float4(0.f, 0.f, 0.f, 0.f);
        }
        __syncthreads();

        for (int c = 0; c < 32; ++c) {
            if (c + 1 < 32)
                pool_sts(sX + ((c + 1) & 1) * PBUF, g4, tr, v);
            if (c + 2 < 32) {
                int e = (c + 2) * 32 + g4;
#pragma unroll
                for (int k = 0; k < 8; ++k) {
                    int trow = t0 + tr + 32 * k;
                    v[k] = (trow < T_LEN && e + 3 < E_NUM)
                           ? *(const float4*)(S_e + (size_t)(b * T_LEN + trow) * E_NUM + e)
                           : make_float4(0.f, 0.f, 0.f, 0.f);
                }
            }
            pool_compute_chunk(sX + (c & 1) * PBUF, g_CTe + c * 256, tid, acc);
            __syncthreads();
        }
        if (tvalid) {
            float* dst = &g_syn_e[(b * SUB_NO) * T_LEN + t];
#pragma unroll
            for (int sp = 0; sp < 4; ++sp) {
                dst[(2 * sp) * T_LEN]     = acc[sp].x;
                dst[(2 * sp + 1) * T_LEN] = acc[sp].y;
            }
        }
    }

    // ================= I: 8 chunks of 32 e =================
    // S_i rows are 1000B (8-aligned only) -> compose float4 from two float2.
    {
#pragma unroll
        for (int sp = 0; sp < 4; ++sp) acc[sp] = make_float2(0.f, 0.f);

        // chunk 0
#pragma unroll
        for (int k = 0; k < 8; ++k) {
            int trow = t0 + tr + 32 * k;
            if (trow < T_LEN) {
                const float* row = S_i + (size_t)(b * T_LEN + trow) * I_NUM + g4;
                float2 lo = *(const float2*)(row);
                float2 hi = *(const float2*)(row + 2);
                v[k] = make_float4(lo.x, lo.y, hi.x, hi.y);
            } else v[k] = make_float4(0.f, 0.f, 0.f, 0.f);
        }
        pool_sts(sX, g4, tr, v);
        // chunk 1
#pragma unroll
        for (int k = 0; k < 8; ++k) {
            int trow = t0 + tr + 32 * k;
            if (trow < T_LEN) {
                const float* row = S_i + (size_t)(b * T_LEN + trow) * I_NUM + 32 + g4;
                float2 lo = *(const float2*)(row);
                float2 hi = *(const float2*)(row + 2);
                v[k] = make_float4(lo.x, lo.y, hi.x, hi.y);
            } else v[k] = make_float4(0.f, 0.f, 0.f, 0.f);
        }
        __syncthreads();

        for (int c = 0; c < 8; ++c) {
            if (c + 1 < 8)
                pool_sts(sX + ((c + 1) & 1) * PBUF, g4, tr, v);
            if (c + 2 < 8) {
                int e = (c + 2) * 32 + g4;
#pragma unroll
                for (int k = 0; k < 8; ++k) {
                    int trow = t0 + tr + 32 * k;
                    if (trow < T_LEN && e + 3 < I_NUM) {
                        const float* row = S_i + (size_t)(b * T_LEN + trow) * I_NUM + e;
                        float2 lo = *(const float2*)(row);
                        float2 hi = *(const float2*)(row + 2);
                        v[k] = make_float4(lo.x, lo.y, hi.x, hi.y);
                    } else {
                        float a0 = 0.f, a1 = 0.f, a2 = 0.f, a3 = 0.f;
                        if (trow < T_LEN) {
                            const float* row = S_i + (size_t)(b * T_LEN + trow) * I_NUM;
                            if (e + 0 < I_NUM) a0 = row[e + 0];
                            if (e + 1 < I_NUM) a1 = row[e + 1];
                            if (e + 2 < I_NUM) a2 = row[e + 2];
                            if (e + 3 < I_NUM) a3 = row[e + 3];
                        }
                        v[k] = make_float4(a0, a1, a2, a3);
                    }
                }
            }
            pool_compute_chunk(sX + (c & 1) * PBUF, g_CTi + c * 256, tid, acc);
            __syncthreads();
        }
        if (tvalid) {
            float* dst = &g_syn_i[(b * SUB_NO) * T_LEN + t];
#pragma unroll
            for (int sp = 0; sp < 4; ++sp) {
                dst[(2 * sp) * T_LEN]     = acc[sp].x;
                dst[(2 * sp + 1) * T_LEN] = acc[sp].y;
            }
        }
    }
}

// ---------------- K3: causal conv + tanh + readout (fma-bound) ----------------
#define CROWS 2
#define TC (256 * CROWS)      // 512
#define XW (TC + T_NO)        // 712

__global__ void __launch_bounds__(256, 4)
conv_kernel(const float* __restrict__ W2,
            const float* __restrict__ b1,
            float* __restrict__ out) {
    __shared__ __align__(16) float4 sKe[T_NO * 4];   // [tau][4 float4] = 16 h
    __shared__ __align__(16) float4 sKi[T_NO * 4];
    __shared__ float sXe[XW], sXi[XW];
    __shared__ float sEw2[HID_NO], sB1[HID_NO];

    int tid = threadIdx.x;
    int bs = blockIdx.y;
    int b = bs >> 3, s = bs & 7;
    int t0 = blockIdx.x * TC;

    const float4* ge = (const float4*)g_kern_e + s * (T_NO * 4);
    const float4* gi = (const float4*)g_kern_i + s * (T_NO * 4);
    for (int idx = tid; idx < T_NO * 4; idx += 256) {
        sKe[idx] = ge[idx];
        sKi[idx] = gi[idx];
    }
    for (int idx = tid; idx < XW; idx += 256) {
        int g = t0 - (T_NO - 1) + idx;
        bool ok = (g >= 0) && (g < T_LEN);
        sXe[idx] = ok ? g_syn_e[(b * SUB_NO + s) * T_LEN + g] : 0.0f;
        sXi[idx] = ok ? g_syn_i[(b * SUB_NO + s) * T_LEN + g] : 0.0f;
    }
    if (tid < HID_NO) {
        sEw2[tid] = expf(W2[s * HID_NO + tid]);
        sB1[tid]  = b1[s * HID_NO + tid];
    }
    __syncthreads();

    float2 acc[CROWS][8];
#pragma unroll
    for (int r = 0; r < CROWS; ++r)
#pragma unroll
        for (int hp = 0; hp < 8; ++hp) acc[r][hp] = make_float2(0.f, 0.f);

    int o0 = tid + (T_NO - 1);

#pragma unroll 2
    for (int tau = 0; tau < T_NO; ++tau) {
        float xe0 = sXe[o0 - tau];
        float xe1 = sXe[o0 + 256 - tau];
        float xi0 = sXi[o0 - tau];
        float xi1 = sXi[o0 + 256 - tau];
        float2 ve0 = make_float2(xe0, xe0), ve1 = make_float2(xe1, xe1);
        float2 vi0 = make_float2(xi0, xi0), vi1 = make_float2(xi1, xi1);
#pragma unroll
        for (int q = 0; q < 4; ++q) {
            float4 ke = sKe[tau * 4 + q];
            float4 ki = sKi[tau * 4 + q];
            float2 keA = make_float2(ke.x, ke.y), keB = make_float2(ke.z, ke.w);
            float2 kiA = make_float2(ki.x, ki.y), kiB = make_float2(ki.z, ki.w);
            acc[0][2*q]   = ffma2(keA, ve0, acc[0][2*q]);
            acc[0][2*q+1] = ffma2(keB, ve0, acc[0][2*q+1]);
            acc[0][2*q]   = ffma2(kiA, vi0, acc[0][2*q]);
            acc[0][2*q+1] = ffma2(kiB, vi0, acc[0][2*q+1]);
            acc[1][2*q]   = ffma2(keA, ve1, acc[1][2*q]);
            acc[1][2*q+1] = ffma2(keB, ve1, acc[1][2*q+1]);
            acc[1][2*q]   = ffma2(kiA, vi1, acc[1][2*q]);
            acc[1][2*q+1] = ffma2(kiB, vi1, acc[1][2*q+1]);
        }
    }

    // epilogue: tanh + positive readout -> sub_out[b, t, s]
#pragma unroll
    for (int r = 0; r < CROWS; ++r) {
        int t = t0 + tid + r * 256;
        if (t < T_LEN) {
            float so = 0.0f;
#pragma unroll
            for (int hp = 0; hp < 8; ++hp) {
                so = fmaf(sEw2[2*hp],   tanh_fast(acc[r][hp].x + sB1[2*hp]),   so);
                so = fmaf(sEw2[2*hp+1], tanh_fast(acc[r][hp].y + sB1[2*hp+1]), so);
            }
            out[SUBOUT_OFF + (size_t)(b * T_LEN + t) * SUB_NO + s] = so;
        }
    }
}

// ---------------- K4: final = sum_s sub_out + V_o ----------------
__global__ void final_kernel(const float* __restrict__ V_o, float* __restrict__ out) {
    int idx = blockIdx.x * blockDim.x + threadIdx.x;
    if (idx >= B_NO * T_LEN) return;
    const float4* p = (const float4*)&out[SUBOUT_OFF + (size_t)idx * SUB_NO];
    float4 a = p[0], c = p[1];
    out[FINAL_OFF + idx] = V_o[0] + ((a.x + a.y) + (a.z + a.w)) + ((c.x + c.y) + (c.z + c.w));
}

// ---------------- launch ----------------
extern "C" void kernel_launch(void* const* d_in, const int* in_sizes, int n_in,
                              void* d_out, int out_size) {
    (void)in_sizes; (void)n_in; (void)out_size;
    const float* S_e   = (const float*)d_in[0];
    const float* S_i   = (const float*)d_in[1];
    const float* Es    = (const float*)d_in[2];
    const float* Is    = (const float*)d_in[3];
    const float* W_e   = (const float*)d_in[4];
    const float* W_i   = (const float*)d_in[5];
    const float* W2    = (const float*)d_in[6];
    const float* b1    = (const float*)d_in[7];
    const float* Cer   = (const float*)d_in[8];
    const float* Cir   = (const float*)d_in[9];
    const float* V_o   = (const float*)d_in[10];
    float* out = (float*)d_out;

    softmax_kernel<<<(E_NUM + I_NUM + 30 + 255) / 256, 256>>>(Cer, Cir, Es, Is, out);
    kern_kernel<<<T_NO, 128>>>(W_e, W_i);

    cudaFuncSetAttribute(pool_kernel, cudaFuncAttributeMaxDynamicSharedMemorySize, PSME_BYTES);
    dim3 pg((T_LEN + 255) / 256, B_NO);                // 40 x 8 = 320 blocks
    pool_kernel<<<pg, 256, PSME_BYTES>>>(S_e, S_i);

    dim3 cg((T_LEN + TC - 1) / TC, B_NO * SUB_NO);     // 20 x 64
    conv_kernel<<<cg, 256>>>(W2, b1, out);

    final_kernel<<<(B_NO * T_LEN + 255) / 256, 256>>>(V_o, out);
}

// round 11
// speedup vs baseline: 1.5842x; 1.5842x over previous
#include <cuda_runtime.h>
#include <math.h>

#define B_NO   8
#define T_LEN  10000
#define E_NUM  1000
#define I_NUM  250
#define SUB_NO 8
#define HID_NO 16
#define CBAS   30
#define T_NO   200

// output layout: final | sub_out | C_syn_e | C_syn_i
#define FINAL_OFF  0
#define SUBOUT_OFF (B_NO * T_LEN)                       // 80000
#define CE_OFF     (SUBOUT_OFF + B_NO * T_LEN * SUB_NO) // 720000
#define CI_OFF     (CE_OFF + SUB_NO * E_NUM)            // 728000

// ---------------- device scratch ----------------
__device__ __align__(16) float g_kern_e[SUB_NO * T_NO * HID_NO];  // [s][tau][h]
__device__ __align__(16) float g_kern_i[SUB_NO * T_NO * HID_NO];
__device__ float g_syn_e[B_NO * SUB_NO * T_LEN];                  // [b][s][t]
__device__ float g_syn_i[B_NO * SUB_NO * T_LEN];
// scaled C in s-pair layout: g_C2e[sp*1024 + e] = {C[2sp][e], C[2sp+1][e]} * exp(scale)
__device__ __align__(16) float2 g_C2e[4 * 1024];   // e-padded with zeros
__device__ __align__(16) float2 g_C2i[4 * 256];

// ---------------- helpers ----------------
__device__ __forceinline__ float2 ffma2(float2 a, float2 b, float2 c) {
    union U { float2 f; unsigned long long u; };
    U A, B, C, D;
    A.f = a; B.f = b; C.f = c;
    asm("fma.rn.f32x2 %0, %1, %2, %3;" : "=l"(D.u) : "l"(A.u), "l"(B.u), "l"(C.u));
    return D.f;
}

__device__ __forceinline__ float tanh_fast(float x) {
    float e = __expf(2.0f * x);
    return 1.0f - __fdividef(2.0f, e + 1.0f);
}

__device__ __forceinline__ float2 shfl_xor_f2(float2 v, int m) {
    union { float2 f; double d; } u;
    u.f = v;
    u.d = __shfl_xor_sync(0xffffffffu, u.d, m);
    return u.f;
}

// Halving-tree reduction of 16 float2 values across 32 lanes.
// On exit lane L holds (in a[0]) the full sum of value index (L & 15).
__device__ __forceinline__ void tree_reduce16(float2 (&a)[16], int lane) {
#pragma unroll
    for (int v = 0; v < 16; ++v) {
        float2 o = shfl_xor_f2(a[v], 16);
        a[v].x += o.x; a[v].y += o.y;
    }
#pragma unroll
    for (int v = 0; v < 8; ++v) {
        float2 send = (lane & 8) ? a[v] : a[v + 8];
        float2 o = shfl_xor_f2(send, 8);
        float2 keep = (lane & 8) ? a[v + 8] : a[v];
        a[v] = make_float2(keep.x + o.x, keep.y + o.y);
    }
#pragma unroll
    for (int v = 0; v < 4; ++v) {
        float2 send = (lane & 4) ? a[v] : a[v + 4];
        float2 o = shfl_xor_f2(send, 4);
        float2 keep = (lane & 4) ? a[v + 4] : a[v];
        a[v] = make_float2(keep.x + o.x, keep.y + o.y);
    }
#pragma unroll
    for (int v = 0; v < 2; ++v) {
        float2 send = (lane & 2) ? a[v] : a[v + 2];
        float2 o = shfl_xor_f2(send, 2);
        float2 keep = (lane & 2) ? a[v + 2] : a[v];
        a[v] = make_float2(keep.x + o.x, keep.y + o.y);
    }
    {
        float2 send = (lane & 1) ? a[0] : a[1];
        float2 o = shfl_xor_f2(send, 1);
        float2 keep = (lane & 1) ? a[1] : a[0];
        a[0] = make_float2(keep.x + o.x, keep.y + o.y);
    }
}

// ---------------- K0: softmax + scaled pair-layout copies (+padding zero) --------
__global__ void softmax_kernel(const float* __restrict__ Cer,
                               const float* __restrict__ Cir,
                               const float* __restrict__ Es,
                               const float* __restrict__ Is,
                               float* __restrict__ out) {
    int idx = blockIdx.x * blockDim.x + threadIdx.x;
    if (idx < E_NUM) {
        float u[SUB_NO], p[SUB_NO];
        float m = -1e30f;
#pragma unroll
        for (int s = 0; s < SUB_NO; ++s) { u[s] = Cer[s * E_NUM + idx] * 10000.0f; m = fmaxf(m, u[s]); }
        float sum = 0.0f;
#pragma unroll
        for (int s = 0; s < SUB_NO; ++s) { p[s] = expf(u[s] - m); sum += p[s]; }
        float inv = 1.0f / sum;
        float sc  = expf(Es[idx]);
        float v[SUB_NO];
#pragma unroll
        for (int s = 0; s < SUB_NO; ++s) {
            v[s] = p[s] * inv;
            out[CE_OFF + s * E_NUM + idx] = v[s];
        }
#pragma unroll
        for (int sp = 0; sp < 4; ++sp)
            g_C2e[sp * 1024 + idx] = make_float2(v[2 * sp] * sc, v[2 * sp + 1] * sc);
    } else if (idx < E_NUM + I_NUM) {
        int j = idx - E_NUM;
        float u[SUB_NO], p[SUB_NO];
        float m = -1e30f;
#pragma unroll
        for (int s = 0; s < SUB_NO; ++s) { u[s] = Cir[s * I_NUM + j] * 10000.0f; m = fmaxf(m, u[s]); }
        float sum = 0.0f;
#pragma unroll
        for (int s = 0; s < SUB_NO; ++s) { p[s] = expf(u[s] - m); sum += p[s]; }
        float inv = 1.0f / sum;
        float sc  = expf(Is[j]);
        float v[SUB_NO];
#pragma unroll
        for (int s = 0; s < SUB_NO; ++s) {
            v[s] = p[s] * inv;
            out[CI_OFF + s * I_NUM + j] = v[s];
        }
#pragma unroll
        for (int sp = 0; sp < 4; ++sp)
            g_C2i[sp * 256 + j] = make_float2(v[2 * sp] * sc, v[2 * sp + 1] * sc);
    } else if (idx < E_NUM + I_NUM + 24) {       // zero-pad C_e rows [1000,1024)
        int row = 1000 + (idx - (E_NUM + I_NUM));
#pragma unroll
        for (int sp = 0; sp < 4; ++sp) g_C2e[sp * 1024 + row] = make_float2(0.f, 0.f);
    } else if (idx < E_NUM + I_NUM + 24 + 6) {   // zero-pad C_i rows [250,256)
        int row = 250 + (idx - (E_NUM + I_NUM + 24));
#pragma unroll
        for (int sp = 0; sp < 4; ++sp) g_C2i[sp * 256 + row] = make_float2(0.f, 0.f);
    }
}

// ---------------- K1: temporal kernels from cosine basis ----------------
__global__ void kern_kernel(const float* __restrict__ W_e,
                            const float* __restrict__ W_i) {
    __shared__ float bas[CBAS];
    int tau = blockIdx.x;
    if (threadIdx.x < CBAS) {
        double phi = 0.5 * M_PI * (double)threadIdx.x;
        double raw = 7.5 * log((double)tau + 1.0 + 1e-7);
        double v = 0.0;
        if (raw >= phi - M_PI && raw <= phi + M_PI)
            v = 0.5 * cos(raw - phi) + 0.5;
        bas[threadIdx.x] = (float)v;
    }
    __syncthreads();
    int r = threadIdx.x;             // 0..127
    float ae = 0.0f, ai = 0.0f;
#pragma unroll
    for (int c = 0; c < CBAS; ++c) {
        ae = fmaf(W_e[r * CBAS + c], bas[c], ae);
        ai = fmaf(W_i[r * CBAS + c], bas[c], ai);
    }
    int s = r >> 4, h = r & 15;
    g_kern_e[(s * T_NO + tau) * HID_NO + h] = ae;
    g_kern_i[(s * T_NO + tau) * HID_NO + h] = ai;
}

// ---------------- K2: synapse pooling (barrier-free, lanes-over-e) ----------------
// warp tile = 4 t; block = 8 warps = 32 t; grid (313, 8)
__global__ void __launch_bounds__(256, 3)
pool_kernel(const float* __restrict__ S_e, const float* __restrict__ S_i) {
    __shared__ float2 sC2e[4 * 1024];   // 32KB
    __shared__ float2 sC2i[4 * 256];    //  8KB

    int tid = threadIdx.x, lane = tid & 31, warp = tid >> 5;
    for (int i = tid; i < 2048; i += 256)
        ((float4*)sC2e)[i] = ((const float4*)g_C2e)[i];
    for (int i = tid; i < 512; i += 256)
        ((float4*)sC2i)[i] = ((const float4*)g_C2i)[i];
    __syncthreads();

    int b = blockIdx.y;
    int t0 = blockIdx.x * 32 + warp * 4;
    const float* Se = S_e + (size_t)b * T_LEN * E_NUM;
    const float* Si = S_i + (size_t)b * T_LEN * I_NUM;

    float2 a[16];

    // ================= E =================
#pragma unroll
    for (int v = 0; v < 16; ++v) a[v] = make_float2(0.f, 0.f);

#pragma unroll 2
    for (int kk = 0; kk < 1024; kk += 64) {
        int eA = kk + lane, eB = kk + 32 + lane;
        float xA[4], xB[4];
#pragma unroll
        for (int i = 0; i < 4; ++i) {
            int t = t0 + i;
            bool tv = (t < T_LEN);
            const float* row = Se + (size_t)t * E_NUM;
            xA[i] = (tv && eA < E_NUM) ? __ldg(row + eA) : 0.f;
            xB[i] = (tv && eB < E_NUM) ? __ldg(row + eB) : 0.f;
        }
        float2 cA[4], cB[4];
#pragma unroll
        for (int sp = 0; sp < 4; ++sp) {
            cA[sp] = sC2e[sp * 1024 + eA];
            cB[sp] = sC2e[sp * 1024 + eB];
        }
#pragma unroll
        for (int i = 0; i < 4; ++i) {
            float2 vA = make_float2(xA[i], xA[i]);
            float2 vB = make_float2(xB[i], xB[i]);
#pragma unroll
            for (int sp = 0; sp < 4; ++sp) {
                a[i * 4 + sp] = ffma2(cA[sp], vA, a[i * 4 + sp]);
                a[i * 4 + sp] = ffma2(cB[sp], vB, a[i * 4 + sp]);
            }
        }
    }
    tree_reduce16(a, lane);
    if (lane < 16) {
        int i = (lane >> 2) & 3, sp = lane & 3;
        int t = t0 + i;
        if (t < T_LEN) {
            float* d = &g_syn_e[(b * SUB_NO) * T_LEN];
            d[(2 * sp) * T_LEN + t]     = a[0].x;
            d[(2 * sp + 1) * T_LEN + t] = a[0].y;
        }
    }

    // ================= I =================
#pragma unroll
    for (int v = 0; v < 16; ++v) a[v] = make_float2(0.f, 0.f);

#pragma unroll 2
    for (int kk = 0; kk < 256; kk += 64) {
        int eA = kk + lane, eB = kk + 32 + lane;
        float xA[4], xB[4];
#pragma unroll
        for (int i = 0; i < 4; ++i) {
            int t = t0 + i;
            bool tv = (t < T_LEN);
            const float* row = Si + (size_t)t * I_NUM;
            xA[i] = (tv && eA < I_NUM) ? __ldg(row + eA) : 0.f;
            xB[i] = (tv && eB < I_NUM) ? __ldg(row + eB) : 0.f;
        }
        float2 cA[4], cB[4];
#pragma unroll
        for (int sp = 0; sp < 4; ++sp) {
            cA[sp] = sC2i[sp * 256 + eA];
            cB[sp] = sC2i[sp * 256 + eB];
        }
#pragma unroll
        for (int i = 0; i < 4; ++i) {
            float2 vA = make_float2(xA[i], xA[i]);
            float2 vB = make_float2(xB[i], xB[i]);
#pragma unroll
            for (int sp = 0; sp < 4; ++sp) {
                a[i * 4 + sp] = ffma2(cA[sp], vA, a[i * 4 + sp]);
                a[i * 4 + sp] = ffma2(cB[sp], vB, a[i * 4 + sp]);
            }
        }
    }
    tree_reduce16(a, lane);
    if (lane < 16) {
        int i = (lane >> 2) & 3, sp = lane & 3;
        int t = t0 + i;
        if (t < T_LEN) {
            float* d = &g_syn_i[(b * SUB_NO) * T_LEN];
            d[(2 * sp) * T_LEN + t]     = a[0].x;
            d[(2 * sp + 1) * T_LEN + t] = a[0].y;
        }
    }
}

// ---------------- K3: causal conv + tanh + readout (R5 verbatim) ----------------
#define TC 512
#define XW (TC + T_NO)   // 712

__global__ void __launch_bounds__(256, 2)
conv_kernel(const float* __restrict__ W2,
            const float* __restrict__ b1,
            float* __restrict__ out) {
    __shared__ __align__(16) float sKe[T_NO * HID_NO];   // [tau][h]
    __shared__ __align__(16) float sKi[T_NO * HID_NO];
    __shared__ float sXe[XW], sXi[XW];
    __shared__ float sEw2[HID_NO], sB1[HID_NO];

    int tid = threadIdx.x;
    int bs = blockIdx.y;
    int b = bs >> 3, s = bs & 7;
    int t0 = blockIdx.x * TC;

    for (int idx = tid; idx < T_NO * HID_NO; idx += 256) {
        sKe[idx] = g_kern_e[s * T_NO * HID_NO + idx];
        sKi[idx] = g_kern_i[s * T_NO * HID_NO + idx];
    }
    for (int idx = tid; idx < XW; idx += 256) {
        int g = t0 - (T_NO - 1) + idx;
        bool ok = (g >= 0) && (g < T_LEN);
        sXe[idx] = ok ? g_syn_e[(b * SUB_NO + s) * T_LEN + g] : 0.0f;
        sXi[idx] = ok ? g_syn_i[(b * SUB_NO + s) * T_LEN + g] : 0.0f;
    }
    if (tid < HID_NO) {
        sEw2[tid] = expf(W2[s * HID_NO + tid]);
        sB1[tid]  = b1[s * HID_NO + tid];
    }
    __syncthreads();

    float2 acc0[8], acc1[8];
#pragma unroll
    for (int hp = 0; hp < 8; ++hp) {
        acc0[hp] = make_float2(0.0f, 0.0f);
        acc1[hp] = make_float2(0.0f, 0.0f);
    }

    int o0 = tid + (T_NO - 1);
    int o1 = tid + 256 + (T_NO - 1);

#pragma unroll 2
    for (int tau = 0; tau < T_NO; ++tau) {
        float xe0 = sXe[o0 - tau], xe1 = sXe[o1 - tau];
        float xi0 = sXi[o0 - tau], xi1 = sXi[o1 - tau];
        float2 ve0 = make_float2(xe0, xe0), ve1 = make_float2(xe1, xe1);
        float2 vi0 = make_float2(xi0, xi0), vi1 = make_float2(xi1, xi1);
        const float2* k_e = reinterpret_cast<const float2*>(&sKe[tau * HID_NO]);
        const float2* k_i = reinterpret_cast<const float2*>(&sKi[tau * HID_NO]);
#pragma unroll
        for (int hp = 0; hp < 8; ++hp) {
            float2 ke = k_e[hp], ki = k_i[hp];
            acc0[hp] = ffma2(ke, ve0, acc0[hp]);
            acc0[hp] = ffma2(ki, vi0, acc0[hp]);
            acc1[hp] = ffma2(ke, ve1, acc1[hp]);
            acc1[hp] = ffma2(ki, vi1, acc1[hp]);
        }
    }

    {
        int t = t0 + tid;
        if (t < T_LEN) {
            float so = 0.0f;
#pragma unroll
            for (int hp = 0; hp < 8; ++hp) {
                so = fmaf(sEw2[2 * hp],     tanh_fast(acc0[hp].x + sB1[2 * hp]),     so);
                so = fmaf(sEw2[2 * hp + 1], tanh_fast(acc0[hp].y + sB1[2 * hp + 1]), so);
            }
            out[SUBOUT_OFF + (size_t)(b * T_LEN + t) * SUB_NO + s] = so;
        }
    }
    {
        int t = t0 + tid + 256;
        if (t < T_LEN) {
            float so = 0.0f;
#pragma unroll
            for (int hp = 0; hp < 8; ++hp) {
                so = fmaf(sEw2[2 * hp],     tanh_fast(acc1[hp].x + sB1[2 * hp]),     so);
                so = fmaf(sEw2[2 * hp + 1], tanh_fast(acc1[hp].y + sB1[2 * hp + 1]), so);
            }
            out[SUBOUT_OFF + (size_t)(b * T_LEN + t) * SUB_NO + s] = so;
        }
    }
}

// ---------------- K4: final = sum_s sub_out + V_o ----------------
__global__ void final_kernel(const float* __restrict__ V_o, float* __restrict__ out) {
    int idx = blockIdx.x * blockDim.x + threadIdx.x;
    if (idx >= B_NO * T_LEN) return;
    const float4* p = (const float4*)&out[SUBOUT_OFF + (size_t)idx * SUB_NO];
    float4 a = p[0], c = p[1];
    out[FINAL_OFF + idx] = V_o[0] + ((a.x + a.y) + (a.z + a.w)) + ((c.x + c.y) + (c.z + c.w));
}

// ---------------- launch ----------------
extern "C" void kernel_launch(void* const* d_in, const int* in_sizes, int n_in,
                              void* d_out, int out_size) {
    (void)in_sizes; (void)n_in; (void)out_size;
    const float* S_e   = (const float*)d_in[0];
    const float* S_i   = (const float*)d_in[1];
    const float* Es    = (const float*)d_in[2];
    const float* Is    = (const float*)d_in[3];
    const float* W_e   = (const float*)d_in[4];
    const float* W_i   = (const float*)d_in[5];
    const float* W2    = (const float*)d_in[6];
    const float* b1    = (const float*)d_in[7];
    const float* Cer   = (const float*)d_in[8];
    const float* Cir   = (const float*)d_in[9];
    const float* V_o   = (const float*)d_in[10];
    float* out = (float*)d_out;

    softmax_kernel<<<(E_NUM + I_NUM + 30 + 255) / 256, 256>>>(Cer, Cir, Es, Is, out);
    kern_kernel<<<T_NO, 128>>>(W_e, W_i);

    dim3 pg((T_LEN + 31) / 32, B_NO);                  // 313 x 8 = 2504 blocks
    pool_kernel<<<pg, 256>>>(S_e, S_i);

    dim3 cg((T_LEN + TC - 1) / TC, B_NO * SUB_NO);     // 20 x 64
    conv_kernel<<<cg, 256>>>(W2, b1, out);

    final_kernel<<<(B_NO * T_LEN + 255) / 256, 256>>>(V_o, out);
}

// round 13
// speedup vs baseline: 1.5844x; 1.0001x over previous
#include <cuda_runtime.h>
#include <math.h>

#define B_NO   8
#define T_LEN  10000
#define E_NUM  1000
#define I_NUM  250
#define SUB_NO 8
#define HID_NO 16
#define CBAS   30
#define T_NO   200

// output layout: final | sub_out | C_syn_e | C_syn_i
#define FINAL_OFF  0
#define SUBOUT_OFF (B_NO * T_LEN)                       // 80000
#define CE_OFF     (SUBOUT_OFF + B_NO * T_LEN * SUB_NO) // 720000
#define CI_OFF     (CE_OFF + SUB_NO * E_NUM)            // 728000

// ---------------- device scratch ----------------
__device__ __align__(16) float g_kern_e[SUB_NO * T_NO * HID_NO];  // [s][tau][h]
__device__ __align__(16) float g_kern_i[SUB_NO * T_NO * HID_NO];
__device__ float g_syn_e[B_NO * SUB_NO * T_LEN];                  // [b][s][t]
__device__ float g_syn_i[B_NO * SUB_NO * T_LEN];
// scaled C in s-pair layout: g_C2e[sp*1024 + e] = {C[2sp][e], C[2sp+1][e]} * exp(scale)
__device__ __align__(16) float2 g_C2e[4 * 1024];   // e-padded with zeros
__device__ __align__(16) float2 g_C2i[4 * 256];

// ---------------- helpers ----------------
__device__ __forceinline__ float2 ffma2(float2 a, float2 b, float2 c) {
    union U { float2 f; unsigned long long u; };
    U A, B, C, D;
    A.f = a; B.f = b; C.f = c;
    asm("fma.rn.f32x2 %0, %1, %2, %3;" : "=l"(D.u) : "l"(A.u), "l"(B.u), "l"(C.u));
    return D.f;
}

__device__ __forceinline__ float tanh_fast(float x) {
    float e = __expf(2.0f * x);
    return 1.0f - __fdividef(2.0f, e + 1.0f);
}

__device__ __forceinline__ float2 shfl_xor_f2(float2 v, int m) {
    union { float2 f; double d; } u;
    u.f = v;
    u.d = __shfl_xor_sync(0xffffffffu, u.d, m);
    return u.f;
}

// Halving-tree reduction of 16 float2 values across 32 lanes.
// On exit lane L holds (in a[0]) the full sum of value index (L & 15).
__device__ __forceinline__ void tree_reduce16(float2 (&a)[16], int lane) {
#pragma unroll
    for (int v = 0; v < 16; ++v) {
        float2 o = shfl_xor_f2(a[v], 16);
        a[v].x += o.x; a[v].y += o.y;
    }
#pragma unroll
    for (int v = 0; v < 8; ++v) {
        float2 send = (lane & 8) ? a[v] : a[v + 8];
        float2 o = shfl_xor_f2(send, 8);
        float2 keep = (lane & 8) ? a[v + 8] : a[v];
        a[v] = make_float2(keep.x + o.x, keep.y + o.y);
    }
#pragma unroll
    for (int v = 0; v < 4; ++v) {
        float2 send = (lane & 4) ? a[v] : a[v + 4];
        float2 o = shfl_xor_f2(send, 4);
        float2 keep = (lane & 4) ? a[v + 4] : a[v];
        a[v] = make_float2(keep.x + o.x, keep.y + o.y);
    }
#pragma unroll
    for (int v = 0; v < 2; ++v) {
        float2 send = (lane & 2) ? a[v] : a[v + 2];
        float2 o = shfl_xor_f2(send, 2);
        float2 keep = (lane & 2) ? a[v + 2] : a[v];
        a[v] = make_float2(keep.x + o.x, keep.y + o.y);
    }
    {
        float2 send = (lane & 1) ? a[0] : a[1];
        float2 o = shfl_xor_f2(send, 1);
        float2 keep = (lane & 1) ? a[1] : a[0];
        a[0] = make_float2(keep.x + o.x, keep.y + o.y);
    }
}

// ---------------- K0: softmax + scaled pair-layout copies (+padding zero) --------
__global__ void softmax_kernel(const float* __restrict__ Cer,
                               const float* __restrict__ Cir,
                               const float* __restrict__ Es,
                               const float* __restrict__ Is,
                               float* __restrict__ out) {
    int idx = blockIdx.x * blockDim.x + threadIdx.x;
    if (idx < E_NUM) {
        float u[SUB_NO], p[SUB_NO];
        float m = -1e30f;
#pragma unroll
        for (int s = 0; s < SUB_NO; ++s) { u[s] = Cer[s * E_NUM + idx] * 10000.0f; m = fmaxf(m, u[s]); }
        float sum = 0.0f;
#pragma unroll
        for (int s = 0; s < SUB_NO; ++s) { p[s] = expf(u[s] - m); sum += p[s]; }
        float inv = 1.0f / sum;
        float sc  = expf(Es[idx]);
        float v[SUB_NO];
#pragma unroll
        for (int s = 0; s < SUB_NO; ++s) {
            v[s] = p[s] * inv;
            out[CE_OFF + s * E_NUM + idx] = v[s];
        }
#pragma unroll
        for (int sp = 0; sp < 4; ++sp)
            g_C2e[sp * 1024 + idx] = make_float2(v[2 * sp] * sc, v[2 * sp + 1] * sc);
    } else if (idx < E_NUM + I_NUM) {
        int j = idx - E_NUM;
        float u[SUB_NO], p[SUB_NO];
        float m = -1e30f;
#pragma unroll
        for (int s = 0; s < SUB_NO; ++s) { u[s] = Cir[s * I_NUM + j] * 10000.0f; m = fmaxf(m, u[s]); }
        float sum = 0.0f;
#pragma unroll
        for (int s = 0; s < SUB_NO; ++s) { p[s] = expf(u[s] - m); sum += p[s]; }
        float inv = 1.0f / sum;
        float sc  = expf(Is[j]);
        float v[SUB_NO];
#pragma unroll
        for (int s = 0; s < SUB_NO; ++s) {
            v[s] = p[s] * inv;
            out[CI_OFF + s * I_NUM + j] = v[s];
        }
#pragma unroll
        for (int sp = 0; sp < 4; ++sp)
            g_C2i[sp * 256 + j] = make_float2(v[2 * sp] * sc, v[2 * sp + 1] * sc);
    } else if (idx < E_NUM + I_NUM + 24) {       // zero-pad C_e rows [1000,1024)
        int row = 1000 + (idx - (E_NUM + I_NUM));
#pragma unroll
        for (int sp = 0; sp < 4; ++sp) g_C2e[sp * 1024 + row] = make_float2(0.f, 0.f);
    } else if (idx < E_NUM + I_NUM + 24 + 6) {   // zero-pad C_i rows [250,256)
        int row = 250 + (idx - (E_NUM + I_NUM + 24));
#pragma unroll
        for (int sp = 0; sp < 4; ++sp) g_C2i[sp * 256 + row] = make_float2(0.f, 0.f);
    }
}

// ---------------- K1: temporal kernels from cosine basis ----------------
__global__ void kern_kernel(const float* __restrict__ W_e,
                            const float* __restrict__ W_i) {
    __shared__ float bas[CBAS];
    int tau = blockIdx.x;
    if (threadIdx.x < CBAS) {
        double phi = 0.5 * M_PI * (double)threadIdx.x;
        double raw = 7.5 * log((double)tau + 1.0 + 1e-7);
        double v = 0.0;
        if (raw >= phi - M_PI && raw <= phi + M_PI)
            v = 0.5 * cos(raw - phi) + 0.5;
        bas[threadIdx.x] = (float)v;
    }
    __syncthreads();
    int r = threadIdx.x;             // 0..127
    float ae = 0.0f, ai = 0.0f;
#pragma unroll
    for (int c = 0; c < CBAS; ++c) {
        ae = fmaf(W_e[r * CBAS + c], bas[c], ae);
        ai = fmaf(W_i[r * CBAS + c], bas[c], ai);
    }
    int s = r >> 4, h = r & 15;
    g_kern_e[(s * T_NO + tau) * HID_NO + h] = ae;
    g_kern_i[(s * T_NO + tau) * HID_NO + h] = ai;
}

// ---------------- K2: synapse pooling (barrier-free, lanes-over-e) ----------------
// warp tile = 4 t; block = 8 warps = 32 t; grid (313, 8)
__global__ void __launch_bounds__(256, 3)
pool_kernel(const float* __restrict__ S_e, const float* __restrict__ S_i) {
    __shared__ float2 sC2e[4 * 1024];   // 32KB
    __shared__ float2 sC2i[4 * 256];    //  8KB

    int tid = threadIdx.x, lane = tid & 31, warp = tid >> 5;
    for (int i = tid; i < 2048; i += 256)
        ((float4*)sC2e)[i] = ((const float4*)g_C2e)[i];
    for (int i = tid; i < 512; i += 256)
        ((float4*)sC2i)[i] = ((const float4*)g_C2i)[i];
    __syncthreads();

    int b = blockIdx.y;
    int t0 = blockIdx.x * 32 + warp * 4;
    const float* Se = S_e + (size_t)b * T_LEN * E_NUM;
    const float* Si = S_i + (size_t)b * T_LEN * I_NUM;

    float2 a[16];

    // ================= E =================
#pragma unroll
    for (int v = 0; v < 16; ++v) a[v] = make_float2(0.f, 0.f);

#pragma unroll 2
    for (int kk = 0; kk < 1024; kk += 64) {
        int eA = kk + lane, eB = kk + 32 + lane;
        float xA[4], xB[4];
#pragma unroll
        for (int i = 0; i < 4; ++i) {
            int t = t0 + i;
            bool tv = (t < T_LEN);
            const float* row = Se + (size_t)t * E_NUM;
            xA[i] = (tv && eA < E_NUM) ? __ldg(row + eA) : 0.f;
            xB[i] = (tv && eB < E_NUM) ? __ldg(row + eB) : 0.f;
        }
        float2 cA[4], cB[4];
#pragma unroll
        for (int sp = 0; sp < 4; ++sp) {
            cA[sp] = sC2e[sp * 1024 + eA];
            cB[sp] = sC2e[sp * 1024 + eB];
        }
#pragma unroll
        for (int i = 0; i < 4; ++i) {
            float2 vA = make_float2(xA[i], xA[i]);
            float2 vB = make_float2(xB[i], xB[i]);
#pragma unroll
            for (int sp = 0; sp < 4; ++sp) {
                a[i * 4 + sp] = ffma2(cA[sp], vA, a[i * 4 + sp]);
                a[i * 4 + sp] = ffma2(cB[sp], vB, a[i * 4 + sp]);
            }
        }
    }
    tree_reduce16(a, lane);
    if (lane < 16) {
        int i = (lane >> 2) & 3, sp = lane & 3;
        int t = t0 + i;
        if (t < T_LEN) {
            float* d = &g_syn_e[(b * SUB_NO) * T_LEN];
            d[(2 * sp) * T_LEN + t]     = a[0].x;
            d[(2 * sp + 1) * T_LEN + t] = a[0].y;
        }
    }

    // ================= I =================
#pragma unroll
    for (int v = 0; v < 16; ++v) a[v] = make_float2(0.f, 0.f);

#pragma unroll 2
    for (int kk = 0; kk < 256; kk += 64) {
        int eA = kk + lane, eB = kk + 32 + lane;
        float xA[4], xB[4];
#pragma unroll
        for (int i = 0; i < 4; ++i) {
            int t = t0 + i;
            bool tv = (t < T_LEN);
            const float* row = Si + (size_t)t * I_NUM;
            xA[i] = (tv && eA < I_NUM) ? __ldg(row + eA) : 0.f;
            xB[i] = (tv && eB < I_NUM) ? __ldg(row + eB) : 0.f;
        }
        float2 cA[4], cB[4];
#pragma unroll
        for (int sp = 0; sp < 4; ++sp) {
            cA[sp] = sC2i[sp * 256 + eA];
            cB[sp] = sC2i[sp * 256 + eB];
        }
#pragma unroll
        for (int i = 0; i < 4; ++i) {
            float2 vA = make_float2(xA[i], xA[i]);
            float2 vB = make_float2(xB[i], xB[i]);
#pragma unroll
            for (int sp = 0; sp < 4; ++sp) {
                a[i * 4 + sp] = ffma2(cA[sp], vA, a[i * 4 + sp]);
                a[i * 4 + sp] = ffma2(cB[sp], vB, a[i * 4 + sp]);
            }
        }
    }
    tree_reduce16(a, lane);
    if (lane < 16) {
        int i = (lane >> 2) & 3, sp = lane & 3;
        int t = t0 + i;
        if (t < T_LEN) {
            float* d = &g_syn_i[(b * SUB_NO) * T_LEN];
            d[(2 * sp) * T_LEN + t]     = a[0].x;
            d[(2 * sp + 1) * T_LEN + t] = a[0].y;
        }
    }
}

// ---------------- K3: causal conv + tanh + readout ----------------
#define TC 512
#define XW (TC + T_NO)   // 712

__global__ void __launch_bounds__(256, 3)
conv_kernel(const float* __restrict__ W2,
            const float* __restrict__ b1,
            float* __restrict__ out) {
    __shared__ __align__(16) float4 sKe[T_NO * 4];   // [tau][4 float4] = 16 h
    __shared__ __align__(16) float4 sKi[T_NO * 4];
    __shared__ float sXe[XW], sXi[XW];
    __shared__ float sEw2[HID_NO], sB1[HID_NO];

    int tid = threadIdx.x;
    int bs = blockIdx.y;
    int b = bs >> 3, s = bs & 7;
    int t0 = blockIdx.x * TC;

    const float4* ge = (const float4*)g_kern_e + s * (T_NO * 4);
    const float4* gi = (const float4*)g_kern_i + s * (T_NO * 4);
    for (int idx = tid; idx < T_NO * 4; idx += 256) {
        sKe[idx] = ge[idx];
        sKi[idx] = gi[idx];
    }
    for (int idx = tid; idx < XW; idx += 256) {
        int g = t0 - (T_NO - 1) + idx;
        bool ok = (g >= 0) && (g < T_LEN);
        sXe[idx] = ok ? g_syn_e[(b * SUB_NO + s) * T_LEN + g] : 0.0f;
        sXi[idx] = ok ? g_syn_i[(b * SUB_NO + s) * T_LEN + g] : 0.0f;
    }
    if (tid < HID_NO) {
        sEw2[tid] = expf(W2[s * HID_NO + tid]);
        sB1[tid]  = b1[s * HID_NO + tid];
    }
    __syncthreads();

    float2 acc0[8], acc1[8];
#pragma unroll
    for (int hp = 0; hp < 8; ++hp) {
        acc0[hp] = make_float2(0.0f, 0.0f);
        acc1[hp] = make_float2(0.0f, 0.0f);
    }

    int o0 = tid + (T_NO - 1);
    int o1 = tid + 256 + (T_NO - 1);

#pragma unroll 2
    for (int tau = 0; tau < T_NO; ++tau) {
        float xe0 = sXe[o0 - tau], xe1 = sXe[o1 - tau];
        float xi0 = sXi[o0 - tau], xi1 = sXi[o1 - tau];
        float2 ve0 = make_float2(xe0, xe0), ve1 = make_float2(xe1, xe1);
        float2 vi0 = make_float2(xi0, xi0), vi1 = make_float2(xi1, xi1);
#pragma unroll
        for (int q = 0; q < 4; ++q) {
            float4 ke = sKe[tau * 4 + q];
            float2 keA = make_float2(ke.x, ke.y), keB = make_float2(ke.z, ke.w);
            acc0[2*q]   = ffma2(keA, ve0, acc0[2*q]);
            acc0[2*q+1] = ffma2(keB, ve0, acc0[2*q+1]);
            acc1[2*q]   = ffma2(keA, ve1, acc1[2*q]);
            acc1[2*q+1] = ffma2(keB, ve1, acc1[2*q+1]);
        }
#pragma unroll
        for (int q = 0; q < 4; ++q) {
            float4 ki = sKi[tau * 4 + q];
            float2 kiA = make_float2(ki.x, ki.y), kiB = make_float2(ki.z, ki.w);
            acc0[2*q]   = ffma2(kiA, vi0, acc0[2*q]);
            acc0[2*q+1] = ffma2(kiB, vi0, acc0[2*q+1]);
            acc1[2*q]   = ffma2(kiA, vi1, acc1[2*q]);
            acc1[2*q+1] = ffma2(kiB, vi1, acc1[2*q+1]);
        }
    }

    // epilogue: tanh + positive readout -> sub_out[b, t, s]
    {
        int t = t0 + tid;
        if (t < T_LEN) {
            float so = 0.0f;
#pragma unroll
            for (int hp = 0; hp < 8; ++hp) {
                so = fmaf(sEw2[2 * hp],     tanh_fast(acc0[hp].x + sB1[2 * hp]),     so);
                so = fmaf(sEw2[2 * hp + 1], tanh_fast(acc0[hp].y + sB1[2 * hp + 1]), so);
            }
            out[SUBOUT_OFF + (size_t)(b * T_LEN + t) * SUB_NO + s] = so;
        }
    }
    {
        int t = t0 + tid + 256;
        if (t < T_LEN) {
            float so = 0.0f;
#pragma unroll
            for (int hp = 0; hp < 8; ++hp) {
                so = fmaf(sEw2[2 * hp],     tanh_fast(acc1[hp].x + sB1[2 * hp]),     so);
                so = fmaf(sEw2[2 * hp + 1], tanh_fast(acc1[hp].y + sB1[2 * hp + 1]), so);
            }
            out[SUBOUT_OFF + (size_t)(b * T_LEN + t) * SUB_NO + s] = so;
        }
    }
}

// ---------------- K4: final = sum_s sub_out + V_o ----------------
__global__ void final_kernel(const float* __restrict__ V_o, float* __restrict__ out) {
    int idx = blockIdx.x * blockDim.x + threadIdx.x;
    if (idx >= B_NO * T_LEN) return;
    const float4* p = (const float4*)&out[SUBOUT_OFF + (size_t)idx * SUB_NO];
    float4 a = p[0], c = p[1];
    out[FINAL_OFF + idx] = V_o[0] + ((a.x + a.y) + (a.z + a.w)) + ((c.x + c.y) + (c.z + c.w));
}

// ---------------- launch ----------------
extern "C" void kernel_launch(void* const* d_in, const int* in_sizes, int n_in,
                              void* d_out, int out_size) {
    (void)in_sizes; (void)n_in; (void)out_size;
    const float* S_e   = (const float*)d_in[0];
    const float* S_i   = (const float*)d_in[1];
    const float* Es    = (const float*)d_in[2];
    const float* Is    = (const float*)d_in[3];
    const float* W_e   = (const float*)d_in[4];
    const float* W_i   = (const float*)d_in[5];
    const float* W2    = (const float*)d_in[6];
    const float* b1    = (const float*)d_in[7];
    const float* Cer   = (const float*)d_in[8];
    const float* Cir   = (const float*)d_in[9];
    const float* V_o   = (const float*)d_in[10];
    float* out = (float*)d_out;

    softmax_kernel<<<(E_NUM + I_NUM + 30 + 255) / 256, 256>>>(Cer, Cir, Es, Is, out);
    kern_kernel<<<T_NO, 128>>>(W_e, W_i);

    dim3 pg((T_LEN + 31) / 32, B_NO);                  // 313 x 8 = 2504 blocks
    pool_kernel<<<pg, 256>>>(S_e, S_i);

    dim3 cg((T_LEN + TC - 1) / TC, B_NO * SUB_NO);     // 20 x 64
    conv_kernel<<<cg, 256>>>(W2, b1, out);

    final_kernel<<<(B_NO * T_LEN + 255) / 256, 256>>>(V_o, out);
}